// round 13
// baseline (speedup 1.0000x reference)
#include <cuda_runtime.h>
#include <cstdint>

#define T_SEQ 16384
#define HDIM  512
#define G4    2048
#define NC    16     // cluster size = whole grid (all-to-all via DSMEM)
#define TPB   512    // 16 warps per CTA
#define UPC   32     // units per CTA

typedef unsigned long long ull;

// Precomputed input gates (allocation-guard-legal scratch)
__device__ float g_xgates[(size_t)T_SEQ * G4];

// ---------------------------------------------------------------------------
// GEMM: g_xgates[t][j] = dot(input[t,:], w_ih[j,:]) + b_ih[j]  (unchanged)
// ---------------------------------------------------------------------------
__global__ __launch_bounds__(256) void gemm_xgates_kernel(
    const float* __restrict__ A, const float* __restrict__ W,
    const float* __restrict__ bias)
{
    __shared__ float As[8][128];
    __shared__ float Ws[8][128];
    const int bm = blockIdx.y * 128;
    const int bn = blockIdx.x * 128;
    const int tid = threadIdx.x;
    const int lr = tid >> 1;
    const int lc = (tid & 1) << 2;
    const int tx = tid & 15;
    const int ty = tid >> 4;

    float acc[8][8];
#pragma unroll
    for (int i = 0; i < 8; i++)
#pragma unroll
        for (int j = 0; j < 8; j++) acc[i][j] = 0.0f;

    const float* Aptr = A + (size_t)(bm + lr) * HDIM + lc;
    const float* Wptr = W + (size_t)(bn + lr) * HDIM + lc;

    for (int k0 = 0; k0 < HDIM; k0 += 8) {
        float4 av = *(const float4*)(Aptr + k0);
        float4 wv = *(const float4*)(Wptr + k0);
        __syncthreads();
        As[lc + 0][lr] = av.x; As[lc + 1][lr] = av.y;
        As[lc + 2][lr] = av.z; As[lc + 3][lr] = av.w;
        Ws[lc + 0][lr] = wv.x; Ws[lc + 1][lr] = wv.y;
        Ws[lc + 2][lr] = wv.z; Ws[lc + 3][lr] = wv.w;
        __syncthreads();
#pragma unroll
        for (int k = 0; k < 8; k++) {
            float a[8], b[8];
            *(float4*)(a)     = *(const float4*)&As[k][ty * 8];
            *(float4*)(a + 4) = *(const float4*)&As[k][ty * 8 + 4];
            *(float4*)(b)     = *(const float4*)&Ws[k][tx * 8];
            *(float4*)(b + 4) = *(const float4*)&Ws[k][tx * 8 + 4];
#pragma unroll
            for (int i = 0; i < 8; i++)
#pragma unroll
                for (int j = 0; j < 8; j++)
                    acc[i][j] = fmaf(a[i], b[j], acc[i][j]);
        }
    }

    float bb[8];
    *(float4*)(bb)     = *(const float4*)&bias[bn + tx * 8];
    *(float4*)(bb + 4) = *(const float4*)&bias[bn + tx * 8 + 4];
#pragma unroll
    for (int i = 0; i < 8; i++) {
        float* cp = g_xgates + (size_t)(bm + ty * 8 + i) * G4 + bn + tx * 8;
        float4 v0 = make_float4(acc[i][0] + bb[0], acc[i][1] + bb[1],
                                acc[i][2] + bb[2], acc[i][3] + bb[3]);
        float4 v1 = make_float4(acc[i][4] + bb[4], acc[i][5] + bb[5],
                                acc[i][6] + bb[6], acc[i][7] + bb[7]);
        *(float4*)cp       = v0;
        *(float4*)(cp + 4) = v1;
    }
}

// ---------------------------------------------------------------------------
// Cluster recurrent kernel — R10 topology (16 CTAs x 512, DSMEM push with
// parity-LSB tags, trailing cluster barrier), with a rebuilt compute/poll
// engine:
//   * two-phase arrival: 128 detector threads spin on ONE v4 granule each
//     (32x less crossbar traffic than R10's all-thread 8xLDS.128 sweeps),
//     then __syncthreads, then a SINGLE bulk h read with plain LDS
//   * fma.rn.f32x2 packed FMA (FFMA2): halves FMA issue; weights and h are
//     handled as b64 pairs (ulonglong2 LDS views, zero packing movs)
// ---------------------------------------------------------------------------
#define HBUF_WORDS 576         // 16 groups x 36 words (32 h + 4 pad)
#define WSM_STRIDE 68          // 64 weights + 4 pad words per thread
#define SMEM_BYTES ((2 * HBUF_WORDS + TPB * WSM_STRIDE) * 4)

__device__ __forceinline__ float sigmoid_fast(float x) {
    return __fdividef(1.0f, 1.0f + __expf(-x));
}
__device__ __forceinline__ float tanh_fast(float x) {
    return 1.0f - __fdividef(2.0f, __expf(2.0f * x) + 1.0f);
}
__device__ __forceinline__ uint32_t smem_addr_u32(const void* p) {
    uint32_t a;
    asm("{ .reg .u64 t; cvta.to.shared.u64 t, %1; cvt.u32.u64 %0, t; }"
        : "=r"(a) : "l"(p));
    return a;
}
__device__ __forceinline__ void fma2(ull& d, ull a, ull b) {
    asm("fma.rn.f32x2 %0, %1, %2, %0;" : "+l"(d) : "l"(a), "l"(b));
}
__device__ __forceinline__ float sum2(ull a) {
    return __uint_as_float((unsigned)a) + __uint_as_float((unsigned)(a >> 32));
}

__global__ void __launch_bounds__(TPB, 1) lstm_rec_cluster(
    const float* __restrict__ Whh, float* __restrict__ out)
{
    extern __shared__ float smem[];
    float* hs  = smem;                      // [2][HBUF_WORDS] parity-tagged h
    float* wsm = smem + 2 * HBUF_WORDS;     // [TPB][WSM_STRIDE] g2/g3 weights

    const int tid  = threadIdx.x;
    const int w    = tid >> 5;
    const int l    = tid & 31;
    const int half = l >> 4;
    const int hl   = l & 15;
    uint32_t r;
    asm("mov.u32 %0, %%cluster_ctarank;" : "=r"(r));

    const int u  = (int)r * UPC + 2 * w + half;  // owned unit
    const int c0 = hl * 32;                      // columns for this lane

    // Weights: gates 0,1 -> registers as b64 pairs; gates 2,3 -> own smem,
    // interleaved per float4 slot k: {g2[2k],g2[2k+1],g3[2k],g3[2k+1]}
    ull wp0[16], wp1[16];
    {
        const ull* p0 = (const ull*)(Whh + ((size_t)(0 * HDIM + u)) * HDIM + c0);
        const ull* p1 = (const ull*)(Whh + ((size_t)(1 * HDIM + u)) * HDIM + c0);
#pragma unroll
        for (int k = 0; k < 16; k++) { wp0[k] = p0[k]; wp1[k] = p1[k]; }
        const float* p2 = Whh + ((size_t)(2 * HDIM + u)) * HDIM + c0;
        const float* p3 = Whh + ((size_t)(3 * HDIM + u)) * HDIM + c0;
        float* wp = wsm + tid * WSM_STRIDE;
        for (int k = 0; k < 16; k++) {
            wp[4*k + 0] = p2[2*k];  wp[4*k + 1] = p2[2*k + 1];
            wp[4*k + 2] = p3[2*k];  wp[4*k + 3] = p3[2*k + 1];
        }
    }

    // Init h ring with LSB=1 (first consumes expect parity 0 -> no false+)
    for (int i = tid; i < 2 * HBUF_WORDS; i += TPB)
        ((uint32_t*)hs)[i] = 1u;
    __syncthreads();
    asm volatile("barrier.cluster.arrive.aligned;" ::: "memory");
    asm volatile("barrier.cluster.wait.aligned;"   ::: "memory");

    const uint32_t hs_base = smem_addr_u32(hs);
    // My push target: unit u's padded word in CTA rank==hl's ring
    const int push_word = 36 * (u >> 5) + (u & 31);
    uint32_t rem0, rem1;
    {
        uint32_t loc0 = hs_base + (uint32_t)(0 * HBUF_WORDS + push_word) * 4u;
        uint32_t loc1 = hs_base + (uint32_t)(1 * HBUF_WORDS + push_word) * 4u;
        asm("mapa.shared::cluster.u32 %0, %1, %2;"
            : "=r"(rem0) : "r"(loc0), "r"((uint32_t)hl));
        asm("mapa.shared::cluster.u32 %0, %1, %2;"
            : "=r"(rem1) : "r"(loc1), "r"((uint32_t)hl));
    }
    // Detector address (threads 0..127): granule tid = h words 4*tid..4*tid+4
    const uint32_t det_off =
        (uint32_t)(36 * (tid >> 3) + 4 * (tid & 7)) * 4u;

    const ull* wsp2 = (const ull*)(wsm + tid * WSM_STRIDE);
    float c_state = 0.0f;     // redundantly maintained by all lanes (identical)

    // xg pipeline: lanes hl<4 hold gate hl's pre-activation, one step ahead
    const bool xlane = (hl < 4);
    const float* xbase = g_xgates + (size_t)hl * HDIM + u;
    float xg_cur = 0.0f;
    if (xlane)
        asm volatile("ld.global.cs.b32 %0, [%1];" : "=f"(xg_cur) : "l"(xbase));

    for (int t = 0; t < T_SEQ; t++) {
        float xg_nxt = 0.0f;
        if (xlane) {
            const float* xr = xbase + (size_t)((t + 1 < T_SEQ) ? t + 1 : t) * G4;
            asm volatile("ld.global.cs.b32 %0, [%1];" : "=f"(xg_nxt) : "l"(xr));
        }

        // ---- phase 1: cheap arrival detection (128 threads, 1 v4 each) ----
        ull hb[16];
        if (t > 0) {
            const uint32_t slot = ((uint32_t)(t - 1) & 1u) * (HBUF_WORDS * 4u);
            if (tid < 128) {
                const uint32_t pa  = hs_base + slot + det_off;
                const uint32_t par = ((uint32_t)(t - 1) >> 1) & 1u;
                while (true) {
                    float f0, f1, f2, f3;
                    asm volatile("ld.volatile.shared.v4.f32 {%0,%1,%2,%3}, [%4];"
                        : "=f"(f0), "=f"(f1), "=f"(f2), "=f"(f3) : "r"(pa));
                    uint32_t bad = (__float_as_uint(f0) ^ par) |
                                   (__float_as_uint(f1) ^ par) |
                                   (__float_as_uint(f2) ^ par) |
                                   (__float_as_uint(f3) ^ par);
                    if ((bad & 1u) == 0u) break;
                }
            }
            __syncthreads();   // all granules present; plain LDS is safe now
            // ---- phase 2: single bulk h read (b64 pairs, no re-check) ----
            const uint32_t ra = hs_base + slot + (uint32_t)(36 * hl) * 4u;
#pragma unroll
            for (int k = 0; k < 8; k++) {
                asm("ld.shared.v2.u64 {%0,%1}, [%2];"
                    : "=l"(hb[2*k]), "=l"(hb[2*k + 1])
                    : "r"(ra + (uint32_t)k * 16u));
            }
        } else {
#pragma unroll
            for (int k = 0; k < 16; k++) hb[k] = 0ULL;
        }

        // ---- matvec: 4 gates x 32 cols, packed f32x2 FMA ----
        ull ac0 = 0ULL, ac1 = 0ULL, ac2 = 0ULL, ac3 = 0ULL;
#pragma unroll
        for (int k = 0; k < 16; k++) {
            ull w2, w3;
            asm("ld.shared.v2.u64 {%0,%1}, [%2];"
                : "=l"(w2), "=l"(w3)
                : "r"(smem_addr_u32(wsp2) + (uint32_t)k * 16u));
            fma2(ac0, wp0[k], hb[k]);
            fma2(ac1, wp1[k], hb[k]);
            fma2(ac2, w2,     hb[k]);
            fma2(ac3, w3,     hb[k]);
        }
        float a0 = sum2(ac0), a1 = sum2(ac1), a2 = sum2(ac2), a3 = sum2(ac3);
        // 4-level butterfly within the half-warp
#pragma unroll
        for (int off = 8; off >= 1; off >>= 1) {
            a0 += __shfl_xor_sync(0xffffffffu, a0, off);
            a1 += __shfl_xor_sync(0xffffffffu, a1, off);
            a2 += __shfl_xor_sync(0xffffffffu, a2, off);
            a3 += __shfl_xor_sync(0xffffffffu, a3, off);
        }

        // ---- activations (lanes base+0..3 in parallel, MUFU path) ----
        float act = 0.0f;
        if (xlane) {
            float pre = (hl == 0 ? a0 : hl == 1 ? a1 : hl == 2 ? a2 : a3) + xg_cur;
            act = (hl == 2) ? tanh_fast(pre) : sigmoid_fast(pre);
        }
        const int base = half << 4;
        float iv = __shfl_sync(0xffffffffu, act, base + 0);
        float fv = __shfl_sync(0xffffffffu, act, base + 1);
        float gv = __shfl_sync(0xffffffffu, act, base + 2);
        float ov = __shfl_sync(0xffffffffu, act, base + 3);

        c_state = fv * c_state + iv * gv;
        float hval = ov * tanh_fast(c_state);
        uint32_t hb_pub = (__float_as_uint(hval) & ~1u) |
                          (((uint32_t)t >> 1) & 1u);

        // ---- push: lane hl delivers unit u to CTA rank hl ----
        uint32_t rem = (t & 1) ? rem1 : rem0;
        asm volatile("st.relaxed.cluster.shared::cluster.b32 [%0], %1;"
                     :: "r"(rem), "r"(hb_pub) : "memory");
        if (hl == 0) {
            asm volatile("st.global.cs.b32 [%0], %1;"
                         :: "l"(out + (size_t)t * HDIM + u), "r"(hb_pub)
                         : "memory");
        }
        xg_cur = xg_nxt;
    }

    // Exit-race fix (R10): stay resident until all peer pushes have landed.
    asm volatile("barrier.cluster.arrive.aligned;" ::: "memory");
    asm volatile("barrier.cluster.wait.aligned;"   ::: "memory");
}

// ---------------------------------------------------------------------------
extern "C" void kernel_launch(void* const* d_in, const int* in_sizes, int n_in,
                              void* d_out, int out_size) {
    const float* input = (const float*)d_in[0];  // [T, H]
    const float* w_ih  = (const float*)d_in[1];  // [4H, H]
    const float* w_hh  = (const float*)d_in[2];  // [4H, H]
    const float* b_ih  = (const float*)d_in[3];  // [4H]
    float* out = (float*)d_out;                  // [T, H]
    (void)in_sizes; (void)n_in; (void)out_size;

    dim3 gg(G4 / 128, T_SEQ / 128);
    gemm_xgates_kernel<<<gg, 256>>>(input, w_ih, b_ih);

    cudaFuncSetAttribute(lstm_rec_cluster,
                         cudaFuncAttributeNonPortableClusterSizeAllowed, 1);
    cudaFuncSetAttribute(lstm_rec_cluster,
                         cudaFuncAttributeMaxDynamicSharedMemorySize, SMEM_BYTES);

    cudaLaunchConfig_t cfg = {};
    cfg.gridDim  = dim3(NC, 1, 1);
    cfg.blockDim = dim3(TPB, 1, 1);
    cfg.dynamicSmemBytes = SMEM_BYTES;
    cfg.stream = 0;
    cudaLaunchAttribute attrs[1];
    attrs[0].id = cudaLaunchAttributeClusterDimension;
    attrs[0].val.clusterDim.x = NC;
    attrs[0].val.clusterDim.y = 1;
    attrs[0].val.clusterDim.z = 1;
    cfg.attrs = attrs;
    cfg.numAttrs = 1;
    cudaLaunchKernelEx(&cfg, lstm_rec_cluster, w_hh, out);
}